// round 13
// baseline (speedup 1.0000x reference)
#include <cuda_runtime.h>
#include <math.h>

#define BATCH    64
#define NLEN     1500
#define NFREQ    1251
#define FCHUNK   64
#define NCHUNKS  ((NFREQ + FCHUNK - 1) / FCHUNK)    // 20
#define SEG      16
#define SEGLEN   94                                  // 16*94 = 1504 >= 1500
#define NPAD     (SEG * SEGLEN)                      // 1504
#define SEGU2    (SEGLEN / 2)                        // 47 ulonglong2 per segment

__device__ float2       g_part[BATCH * NCHUNKS * 2]; // per-(batch,chunk,warp) (max,sumexp)
__device__ float        g_tgt[BATCH];                // psd at the argmin grid index
__device__ float        g_per[BATCH];                // per-sample losses
__device__ unsigned int g_pair_ticket[BATCH / 2];    // zero-init; self-resetting
__device__ unsigned int g_ticket;                    // zero-init; self-resetting

// ---- packed f32x2 helpers (sm_103a) ----
__device__ __forceinline__ unsigned long long pk2(float lo, float hi) {
    unsigned long long r;
    asm("mov.b64 %0, {%1, %2};" : "=l"(r) : "f"(lo), "f"(hi));
    return r;
}
__device__ __forceinline__ void upk2(unsigned long long v, float& lo, float& hi) {
    asm("mov.b64 {%0, %1}, %2;" : "=f"(lo), "=f"(hi) : "l"(v));
}
__device__ __forceinline__ unsigned long long fma2(unsigned long long a,
                                                   unsigned long long b,
                                                   unsigned long long c) {
    unsigned long long d;
    asm("fma.rn.f32x2 %0, %1, %2, %3;" : "=l"(d) : "l"(a), "l"(b), "l"(c));
    return d;
}

// Frequency grid value, matching jnp.arange semantics: iota*step + start in f32
__device__ __forceinline__ float grid_f(int i) {
    return __fadd_rn(__fmul_rn((float)i, 0.002f), 0.5f);
}

// Analytic argmin of |grid_f(k) - ft| over k in [0, NFREQ): grid is monotone,
// so scan +/-4 around round((ft-0.5)*500); strict < keeps first occurrence.
__device__ __forceinline__ int argmin_idx(float ft) {
    int k0 = (int)lrintf((ft - 0.5f) * 500.0f);
    k0 = min(max(k0, 0), NFREQ - 1);
    const int klo = max(k0 - 4, 0);
    const int khi = min(k0 + 4, NFREQ - 1);
    float bd = 1e30f;
    int   bi = klo;
    for (int k = klo; k <= khi; k++) {
        const float d = fabsf(grid_f(k) - ft);
        if (d < bd) { bd = d; bi = k; }
    }
    return bi;
}

// ============================================================================
// Single fused kernel.
//  Stage 1 (all 640 blocks): segmented Goertzel (ILP=4, f32x2-packed batch
//    pair). Each sp==0 warp emits a chunk-local (max,sumexp) partial, and the
//    lane owning the batch's analytic argmin index writes g_tgt[b] directly
//    (no psd array at all).
//  Stage 2 (per-pair ticket, last of 20 chunk blocks): merge 40 partials per
//    batch (exact logsumexp merge, one warp per batch), write g_per.
//  Stage 3 (global ticket, last of 32 pairs): mean over 64 -> out.
// Tickets self-reset; fences follow the threadFenceReduction pattern, so the
// kernel is deterministic and graph-replay safe.
// ============================================================================
__global__ void __launch_bounds__(256)
fused_kernel(const float* __restrict__ x, const float* __restrict__ fs,
             const float* __restrict__ f_true, float* __restrict__ out)
{
    // 753 entries: 752 data (+pad) + 1 spare so tail prefetch stays in bounds
    __shared__ __align__(16) char smem_raw[(NPAD / 2 + 1) * 16];
    ulonglong2* sx2 = (ulonglong2*)smem_raw;
    float4*     red = (float4*)smem_raw;     // overlaid AFTER sx2 is dead
    __shared__ int sflag;

    const int tid = threadIdx.x;
    const int bp  = blockIdx.y;              // batch pair 0..31
    const int b0  = 2 * bp;
    const int b1  = 2 * bp + 1;

    const int fl  = tid & (FCHUNK - 1);      // frequency lane 0..63
    const int sp  = tid >> 6;                // segment quad 0..3
    const int f   = blockIdx.x * FCHUNK + fl;
    const int fc  = (f < NFREQ) ? f : (NFREQ - 1);
    const float fval = grid_f(fc);

    const float TWO_PI = 6.283185307179586476925f;
    const float w0 = TWO_PI * fval / fs[b0];
    const float w1 = TWO_PI * fval / fs[b1];
    float c0, sn0, c1, sn1;
    sincosf(w0, &sn0, &c0);
    sincosf(w1, &sn1, &c1);

    // rotation for chain 0 of this quad: phi = -w * (4sp*SEGLEN + SEGLEN-1),
    // per-chain step psi = -w * SEGLEN applied incrementally in the epilogue.
    const float nrot0 = (float)(4 * sp * SEGLEN + SEGLEN - 1);
    float rc0, rs0, rc1, rs1, pc0, ps0, pc1, ps1;
    sincosf(-w0 * nrot0, &rs0, &rc0);
    sincosf(-w1 * nrot0, &rs1, &rc1);
    sincosf(-w0 * (float)SEGLEN, &ps0, &pc0);
    sincosf(-w1 * (float)SEGLEN, &ps1, &pc1);

    // ---- load & pack x: 2 samples per ulonglong2 entry ----
    const float2* __restrict__ x0v = (const float2*)(x + b0 * NLEN);
    const float2* __restrict__ x1v = (const float2*)(x + b1 * NLEN);
    for (int i = tid; i < NLEN / 2; i += 256) {
        const float2 a = x0v[i];
        const float2 b = x1v[i];
        ulonglong2 v;
        v.x = pk2(a.x, b.x);
        v.y = pk2(a.y, b.y);
        sx2[i] = v;
    }
    if (tid < (NPAD - NLEN) / 2 + 1) {       // zero entries 750,751 + spare 752
        ulonglong2 z; z.x = 0ull; z.y = 0ull;
        sx2[NLEN / 2 + tid] = z;
    }
    __syncthreads();

    const unsigned long long coeff = pk2(2.0f * c0, 2.0f * c1);
    const unsigned long long NEG1  = pk2(-1.0f, -1.0f);
    unsigned long long s1A = 0ull, s2A = 0ull, s1B = 0ull, s2B = 0ull;
    unsigned long long s1C = 0ull, s2C = 0ull, s1D = 0ull, s2D = 0ull;

    const ulonglong2* __restrict__ pA = sx2 + (4 * sp) * SEGU2;
    const ulonglong2* __restrict__ pB = pA + SEGU2;
    const ulonglong2* __restrict__ pC = pB + SEGU2;
    const ulonglong2* __restrict__ pD = pC + SEGU2;

    // software-pipelined: prefetch i+1 while computing on i (warp-uniform
    // addresses -> SMEM broadcast, no crossbar pressure)
    ulonglong2 vA = pA[0], vB = pB[0], vC = pC[0], vD = pD[0];
    for (int i = 0; i < SEGU2; i++) {
        const ulonglong2 nA = pA[i + 1];
        const ulonglong2 nB = pB[i + 1];
        const ulonglong2 nC = pC[i + 1];
        const ulonglong2 nD = pD[i + 1];
        unsigned long long t, s;
        // four independent Goertzel chains, interleaved (ILP=4)
        t = fma2(s2A, NEG1, vA.x);  s = fma2(coeff, s1A, t);  s2A = s1A; s1A = s;
        t = fma2(s2B, NEG1, vB.x);  s = fma2(coeff, s1B, t);  s2B = s1B; s1B = s;
        t = fma2(s2C, NEG1, vC.x);  s = fma2(coeff, s1C, t);  s2C = s1C; s1C = s;
        t = fma2(s2D, NEG1, vD.x);  s = fma2(coeff, s1D, t);  s2D = s1D; s1D = s;
        t = fma2(s2A, NEG1, vA.y);  s = fma2(coeff, s1A, t);  s2A = s1A; s1A = s;
        t = fma2(s2B, NEG1, vB.y);  s = fma2(coeff, s1B, t);  s2B = s1B; s1B = s;
        t = fma2(s2C, NEG1, vC.y);  s = fma2(coeff, s1C, t);  s2C = s1C; s1C = s;
        t = fma2(s2D, NEG1, vD.y);  s = fma2(coeff, s1D, t);  s2D = s1D; s1D = s;
        vA = nA; vB = nB; vC = nC; vD = nD;
    }

    // ---- epilogue: per chain P = (s1 - c*s2) + j(sin*s2), rotate & sum ----
    float accRe0 = 0.0f, accIm0 = 0.0f, accRe1 = 0.0f, accIm1 = 0.0f;
    unsigned long long s1s[4] = {s1A, s1B, s1C, s1D};
    unsigned long long s2s[4] = {s2A, s2B, s2C, s2D};
    #pragma unroll
    for (int cch = 0; cch < 4; cch++) {
        float a0, a1, d0, d1;
        upk2(s1s[cch], a0, a1);
        upk2(s2s[cch], d0, d1);
        const float gre0 = a0 - c0 * d0, gim0 = sn0 * d0;
        const float gre1 = a1 - c1 * d1, gim1 = sn1 * d1;
        accRe0 += rc0 * gre0 - rs0 * gim0;
        accIm0 += rc0 * gim0 + rs0 * gre0;
        accRe1 += rc1 * gre1 - rs1 * gim1;
        accIm1 += rc1 * gim1 + rs1 * gre1;
        const float trc0 = rc0 * pc0 - rs0 * ps0;
        rs0 = rc0 * ps0 + rs0 * pc0;  rc0 = trc0;
        const float trc1 = rc1 * pc1 - rs1 * ps1;
        rs1 = rc1 * ps1 + rs1 * pc1;  rc1 = trc1;
    }

    float4 r;
    r.x = accRe0; r.y = accIm0; r.z = accRe1; r.w = accIm1;

    __syncthreads();                         // sx2 dead; red overlay takes over
    if (sp > 0) red[(sp - 1) * FCHUNK + fl] = r;
    __syncthreads();

    if (sp == 0) {
        #pragma unroll
        for (int s = 0; s < 3; s++) {
            const float4 o = red[s * FCHUNK + fl];
            r.x += o.x; r.y += o.y; r.z += o.z; r.w += o.w;
        }
        const bool valid = (f < NFREQ);
        float p0 = valid ? (r.x * r.x + r.y * r.y) : -1e30f;
        float p1 = valid ? (r.z * r.z + r.w * r.w) : -1e30f;

        // write the PSD value at each batch's target grid index (if owned here)
        const int bi0 = argmin_idx(f_true[b0]);
        const int bi1 = argmin_idx(f_true[b1]);
        if (valid && f == bi0) g_tgt[b0] = p0;
        if (valid && f == bi1) g_tgt[b1] = p1;

        // ---- chunk-local softmax partials: per-warp (max, sumexp) ----
        float m0 = p0, m1 = p1;
        #pragma unroll
        for (int o = 16; o > 0; o >>= 1) {
            m0 = fmaxf(m0, __shfl_xor_sync(0xffffffffu, m0, o));
            m1 = fmaxf(m1, __shfl_xor_sync(0xffffffffu, m1, o));
        }
        float e0 = expf(p0 - m0);
        float e1 = expf(p1 - m1);
        #pragma unroll
        for (int o = 16; o > 0; o >>= 1) {
            e0 += __shfl_xor_sync(0xffffffffu, e0, o);
            e1 += __shfl_xor_sync(0xffffffffu, e1, o);
        }
        if ((tid & 31) == 0) {
            const int w = tid >> 5;          // 0 or 1
            g_part[(b0 * NCHUNKS + blockIdx.x) * 2 + w] = make_float2(m0, e0);
            g_part[(b1 * NCHUNKS + blockIdx.x) * 2 + w] = make_float2(m1, e1);
        }
    }

    // ======================================================================
    // Stage 2: elect the last block of this batch pair (threadFenceReduction)
    // ======================================================================
    __syncthreads();                          // all g_part/g_tgt stores issued
    __threadfence();                          // publish them device-wide
    if (tid == 0)
        sflag = (atomicAdd(&g_pair_ticket[bp], 1u) == NCHUNKS - 1) ? 1 : 0;
    __syncthreads();
    if (!sflag) return;
    if (tid == 0) g_pair_ticket[bp] = 0;      // self-reset for graph replay

    // warp 0 -> batch b0, warp 1 -> batch b1; 40 partials each
    const int w  = tid >> 5;
    const int ln = tid & 31;
    if (w < 2) {
        const int myb = w ? b1 : b0;
        const float2* __restrict__ part = g_part + myb * NCHUNKS * 2;
        float2 v0, v1;
        v0.x = __ldcg(&part[ln].x);  v0.y = __ldcg(&part[ln].y);
        if (ln < NCHUNKS * 2 - 32) { v1.x = __ldcg(&part[32 + ln].x); v1.y = __ldcg(&part[32 + ln].y); }
        else                       { v1 = make_float2(-1e30f, 0.0f); }

        float M = fmaxf(v0.x, v1.x);
        #pragma unroll
        for (int o = 16; o > 0; o >>= 1)
            M = fmaxf(M, __shfl_xor_sync(0xffffffffu, M, o));
        float S = v0.y * expf(v0.x - M) + v1.y * expf(v1.x - M);
        #pragma unroll
        for (int o = 16; o > 0; o >>= 1)
            S += __shfl_xor_sync(0xffffffffu, S, o);

        if (ln == 0) {
            const float p = expf(__ldcg(&g_tgt[myb]) - M) / S;   // softmax[idx]
            g_per[myb] = -logf(p + 1e-8f);
        }
    }

    // ======================================================================
    // Stage 3: last pair overall computes the mean
    // ======================================================================
    __threadfence();
    __syncthreads();
    if (tid == 0)
        sflag = (atomicAdd(&g_ticket, 1u) == BATCH / 2 - 1) ? 1 : 0;
    __syncthreads();
    if (!sflag) return;

    if (tid < 32) {
        float v = __ldcg(&g_per[tid]) + __ldcg(&g_per[tid + 32]);
        #pragma unroll
        for (int o = 16; o > 0; o >>= 1)
            v += __shfl_down_sync(0xffffffffu, v, o);
        if (tid == 0) {
            out[0] = v * (1.0f / (float)BATCH);
            g_ticket = 0;                     // self-reset for graph replay
        }
    }
}

// ============================================================================
extern "C" void kernel_launch(void* const* d_in, const int* in_sizes, int n_in,
                              void* d_out, int out_size)
{
    const float* x      = (const float*)d_in[0];   // [64, 1500]
    const float* f_true = (const float*)d_in[1];   // [64]
    const float* fs     = (const float*)d_in[2];   // [64]
    float* out = (float*)d_out;                    // scalar

    dim3 g1(NCHUNKS, BATCH / 2);                   // (20, 32)
    fused_kernel<<<g1, 256>>>(x, fs, f_true, out);
}

// round 14
// speedup vs baseline: 1.0504x; 1.0504x over previous
#include <cuda_runtime.h>
#include <math.h>

#define BATCH    64
#define NLEN     1500
#define NFREQ    1251
#define FCHUNK   32
#define NCHUNKS  ((NFREQ + FCHUNK - 1) / FCHUNK)    // 40
#define SEG      16
#define SEGLEN   94                                  // 16*94 = 1504 >= 1500
#define NPAD     (SEG * SEGLEN)                      // 1504
#define SEGU2    (SEGLEN / 2)                        // 47 ulonglong2 per segment

__device__ float2       g_part[BATCH * NCHUNKS];     // per-(batch,chunk) (max,sumexp)
__device__ float        g_tgt[BATCH];                // psd at the argmin grid index
__device__ float        g_per[BATCH];                // per-sample losses
__device__ unsigned int g_pair_ticket[BATCH / 2];    // zero-init; self-resetting
__device__ unsigned int g_ticket;                    // zero-init; self-resetting

// ---- packed f32x2 helpers (sm_103a) ----
__device__ __forceinline__ unsigned long long pk2(float lo, float hi) {
    unsigned long long r;
    asm("mov.b64 %0, {%1, %2};" : "=l"(r) : "f"(lo), "f"(hi));
    return r;
}
__device__ __forceinline__ void upk2(unsigned long long v, float& lo, float& hi) {
    asm("mov.b64 {%0, %1}, %2;" : "=f"(lo), "=f"(hi) : "l"(v));
}
__device__ __forceinline__ unsigned long long fma2(unsigned long long a,
                                                   unsigned long long b,
                                                   unsigned long long c) {
    unsigned long long d;
    asm("fma.rn.f32x2 %0, %1, %2, %3;" : "=l"(d) : "l"(a), "l"(b), "l"(c));
    return d;
}

// Frequency grid value, matching jnp.arange semantics: iota*step + start in f32
__device__ __forceinline__ float grid_f(int i) {
    return __fadd_rn(__fmul_rn((float)i, 0.002f), 0.5f);
}

// Analytic argmin of |grid_f(k) - ft| over k in [0, NFREQ): grid is monotone,
// so scan +/-4 around round((ft-0.5)*500); strict < keeps first occurrence.
__device__ __forceinline__ int argmin_idx(float ft) {
    int k0 = (int)lrintf((ft - 0.5f) * 500.0f);
    k0 = min(max(k0, 0), NFREQ - 1);
    const int klo = max(k0 - 4, 0);
    const int khi = min(k0 + 4, NFREQ - 1);
    float bd = 1e30f;
    int   bi = klo;
    for (int k = klo; k <= khi; k++) {
        const float d = fabsf(grid_f(k) - ft);
        if (d < bd) { bd = d; bi = k; }
    }
    return bi;
}

// ============================================================================
// Single fused kernel, fine-grained blocks for wave balance.
//  Stage 1 (1280 blocks of 128 thr = 32 freq lanes x 4 segment-quads):
//    segmented Goertzel (ILP=4, f32x2-packed batch pair). Warp 0 emits a
//    chunk-local (max,sumexp) partial; the lane owning each batch's analytic
//    argmin index writes g_tgt[b] directly (no psd array).
//  Stage 2 (per-pair ticket, last of 40 chunk blocks): merge 40 partials per
//    batch (exact logsumexp merge, one warp per batch), write g_per.
//  Stage 3 (global ticket, last of 32 pairs): mean over 64 -> out.
// Tickets self-reset; fences follow the threadFenceReduction pattern.
// ============================================================================
__global__ void __launch_bounds__(128, 8)
fused_kernel(const float* __restrict__ x, const float* __restrict__ fs,
             const float* __restrict__ f_true, float* __restrict__ out)
{
    // 753 entries: 752 data (+pad) + 1 spare so tail prefetch stays in bounds
    __shared__ __align__(16) char smem_raw[(NPAD / 2 + 1) * 16];
    ulonglong2* sx2 = (ulonglong2*)smem_raw;
    float4*     red = (float4*)smem_raw;     // overlaid AFTER sx2 is dead
    __shared__ int sflag;

    const int tid = threadIdx.x;
    const int bp  = blockIdx.y;              // batch pair 0..31
    const int b0  = 2 * bp;
    const int b1  = 2 * bp + 1;

    const int fl  = tid & (FCHUNK - 1);      // frequency lane 0..31
    const int sp  = tid >> 5;                // segment quad 0..3
    const int f   = blockIdx.x * FCHUNK + fl;
    const int fc  = (f < NFREQ) ? f : (NFREQ - 1);
    const float fval = grid_f(fc);

    const float TWO_PI = 6.283185307179586476925f;
    const float w0 = TWO_PI * fval / fs[b0];
    const float w1 = TWO_PI * fval / fs[b1];
    float c0, sn0, c1, sn1;
    sincosf(w0, &sn0, &c0);
    sincosf(w1, &sn1, &c1);

    // rotation for chain 0 of this quad: phi = -w * (4sp*SEGLEN + SEGLEN-1),
    // per-chain step psi = -w * SEGLEN applied incrementally in the epilogue.
    const float nrot0 = (float)(4 * sp * SEGLEN + SEGLEN - 1);
    float rc0, rs0, rc1, rs1, pc0, ps0, pc1, ps1;
    sincosf(-w0 * nrot0, &rs0, &rc0);
    sincosf(-w1 * nrot0, &rs1, &rc1);
    sincosf(-w0 * (float)SEGLEN, &ps0, &pc0);
    sincosf(-w1 * (float)SEGLEN, &ps1, &pc1);

    // ---- load & pack x: 2 samples per ulonglong2 entry ----
    const float2* __restrict__ x0v = (const float2*)(x + b0 * NLEN);
    const float2* __restrict__ x1v = (const float2*)(x + b1 * NLEN);
    for (int i = tid; i < NLEN / 2; i += 128) {
        const float2 a = x0v[i];
        const float2 b = x1v[i];
        ulonglong2 v;
        v.x = pk2(a.x, b.x);
        v.y = pk2(a.y, b.y);
        sx2[i] = v;
    }
    if (tid < (NPAD - NLEN) / 2 + 1) {       // zero entries 750,751 + spare 752
        ulonglong2 z; z.x = 0ull; z.y = 0ull;
        sx2[NLEN / 2 + tid] = z;
    }
    __syncthreads();

    const unsigned long long coeff = pk2(2.0f * c0, 2.0f * c1);
    const unsigned long long NEG1  = pk2(-1.0f, -1.0f);
    unsigned long long s1A = 0ull, s2A = 0ull, s1B = 0ull, s2B = 0ull;
    unsigned long long s1C = 0ull, s2C = 0ull, s1D = 0ull, s2D = 0ull;

    const ulonglong2* __restrict__ pA = sx2 + (4 * sp) * SEGU2;
    const ulonglong2* __restrict__ pB = pA + SEGU2;
    const ulonglong2* __restrict__ pC = pB + SEGU2;
    const ulonglong2* __restrict__ pD = pC + SEGU2;

    // software-pipelined: prefetch i+1 while computing on i (warp-uniform
    // addresses -> SMEM broadcast, no crossbar pressure)
    ulonglong2 vA = pA[0], vB = pB[0], vC = pC[0], vD = pD[0];
    for (int i = 0; i < SEGU2; i++) {
        const ulonglong2 nA = pA[i + 1];
        const ulonglong2 nB = pB[i + 1];
        const ulonglong2 nC = pC[i + 1];
        const ulonglong2 nD = pD[i + 1];
        unsigned long long t, s;
        // four independent Goertzel chains, interleaved (ILP=4)
        t = fma2(s2A, NEG1, vA.x);  s = fma2(coeff, s1A, t);  s2A = s1A; s1A = s;
        t = fma2(s2B, NEG1, vB.x);  s = fma2(coeff, s1B, t);  s2B = s1B; s1B = s;
        t = fma2(s2C, NEG1, vC.x);  s = fma2(coeff, s1C, t);  s2C = s1C; s1C = s;
        t = fma2(s2D, NEG1, vD.x);  s = fma2(coeff, s1D, t);  s2D = s1D; s1D = s;
        t = fma2(s2A, NEG1, vA.y);  s = fma2(coeff, s1A, t);  s2A = s1A; s1A = s;
        t = fma2(s2B, NEG1, vB.y);  s = fma2(coeff, s1B, t);  s2B = s1B; s1B = s;
        t = fma2(s2C, NEG1, vC.y);  s = fma2(coeff, s1C, t);  s2C = s1C; s1C = s;
        t = fma2(s2D, NEG1, vD.y);  s = fma2(coeff, s1D, t);  s2D = s1D; s1D = s;
        vA = nA; vB = nB; vC = nC; vD = nD;
    }

    // ---- epilogue: per chain P = (s1 - c*s2) + j(sin*s2), rotate & sum ----
    float accRe0 = 0.0f, accIm0 = 0.0f, accRe1 = 0.0f, accIm1 = 0.0f;
    unsigned long long s1s[4] = {s1A, s1B, s1C, s1D};
    unsigned long long s2s[4] = {s2A, s2B, s2C, s2D};
    #pragma unroll
    for (int cch = 0; cch < 4; cch++) {
        float a0, a1, d0, d1;
        upk2(s1s[cch], a0, a1);
        upk2(s2s[cch], d0, d1);
        const float gre0 = a0 - c0 * d0, gim0 = sn0 * d0;
        const float gre1 = a1 - c1 * d1, gim1 = sn1 * d1;
        accRe0 += rc0 * gre0 - rs0 * gim0;
        accIm0 += rc0 * gim0 + rs0 * gre0;
        accRe1 += rc1 * gre1 - rs1 * gim1;
        accIm1 += rc1 * gim1 + rs1 * gre1;
        const float trc0 = rc0 * pc0 - rs0 * ps0;
        rs0 = rc0 * ps0 + rs0 * pc0;  rc0 = trc0;
        const float trc1 = rc1 * pc1 - rs1 * ps1;
        rs1 = rc1 * ps1 + rs1 * pc1;  rc1 = trc1;
    }

    float4 r;
    r.x = accRe0; r.y = accIm0; r.z = accRe1; r.w = accIm1;

    __syncthreads();                         // sx2 dead; red overlay takes over
    if (sp > 0) red[(sp - 1) * FCHUNK + fl] = r;
    __syncthreads();

    if (sp == 0) {                           // warp 0 only (32 lanes)
        #pragma unroll
        for (int s = 0; s < 3; s++) {
            const float4 o = red[s * FCHUNK + fl];
            r.x += o.x; r.y += o.y; r.z += o.z; r.w += o.w;
        }
        const bool valid = (f < NFREQ);
        float p0 = valid ? (r.x * r.x + r.y * r.y) : -1e30f;
        float p1 = valid ? (r.z * r.z + r.w * r.w) : -1e30f;

        // write the PSD value at each batch's target grid index (if owned here)
        const int bi0 = argmin_idx(f_true[b0]);
        const int bi1 = argmin_idx(f_true[b1]);
        if (valid && f == bi0) g_tgt[b0] = p0;
        if (valid && f == bi1) g_tgt[b1] = p1;

        // ---- chunk-local softmax partials: warp-wide (max, sumexp) ----
        float m0 = p0, m1 = p1;
        #pragma unroll
        for (int o = 16; o > 0; o >>= 1) {
            m0 = fmaxf(m0, __shfl_xor_sync(0xffffffffu, m0, o));
            m1 = fmaxf(m1, __shfl_xor_sync(0xffffffffu, m1, o));
        }
        float e0 = expf(p0 - m0);
        float e1 = expf(p1 - m1);
        #pragma unroll
        for (int o = 16; o > 0; o >>= 1) {
            e0 += __shfl_xor_sync(0xffffffffu, e0, o);
            e1 += __shfl_xor_sync(0xffffffffu, e1, o);
        }
        if (fl == 0) {
            g_part[b0 * NCHUNKS + blockIdx.x] = make_float2(m0, e0);
            g_part[b1 * NCHUNKS + blockIdx.x] = make_float2(m1, e1);
        }
    }

    // ======================================================================
    // Stage 2: elect the last block of this batch pair (threadFenceReduction)
    // ======================================================================
    __syncthreads();                          // all g_part/g_tgt stores issued
    __threadfence();                          // publish them device-wide
    if (tid == 0)
        sflag = (atomicAdd(&g_pair_ticket[bp], 1u) == NCHUNKS - 1) ? 1 : 0;
    __syncthreads();
    if (!sflag) return;
    if (tid == 0) g_pair_ticket[bp] = 0;      // self-reset for graph replay

    // warp 0 -> batch b0, warp 1 -> batch b1; 40 partials each
    const int w  = tid >> 5;
    const int ln = tid & 31;
    if (w < 2) {
        const int myb = w ? b1 : b0;
        const float2* __restrict__ part = g_part + myb * NCHUNKS;
        float2 v0, v1;
        v0.x = __ldcg(&part[ln].x);  v0.y = __ldcg(&part[ln].y);
        if (ln < NCHUNKS - 32) { v1.x = __ldcg(&part[32 + ln].x); v1.y = __ldcg(&part[32 + ln].y); }
        else                   { v1 = make_float2(-1e30f, 0.0f); }

        float M = fmaxf(v0.x, v1.x);
        #pragma unroll
        for (int o = 16; o > 0; o >>= 1)
            M = fmaxf(M, __shfl_xor_sync(0xffffffffu, M, o));
        float S = v0.y * expf(v0.x - M) + v1.y * expf(v1.x - M);
        #pragma unroll
        for (int o = 16; o > 0; o >>= 1)
            S += __shfl_xor_sync(0xffffffffu, S, o);

        if (ln == 0) {
            const float p = expf(__ldcg(&g_tgt[myb]) - M) / S;   // softmax[idx]
            g_per[myb] = -logf(p + 1e-8f);
        }
    }

    // ======================================================================
    // Stage 3: last pair overall computes the mean
    // ======================================================================
    __threadfence();
    __syncthreads();
    if (tid == 0)
        sflag = (atomicAdd(&g_ticket, 1u) == BATCH / 2 - 1) ? 1 : 0;
    __syncthreads();
    if (!sflag) return;

    if (tid < 32) {
        float v = __ldcg(&g_per[tid]) + __ldcg(&g_per[tid + 32]);
        #pragma unroll
        for (int o = 16; o > 0; o >>= 1)
            v += __shfl_down_sync(0xffffffffu, v, o);
        if (tid == 0) {
            out[0] = v * (1.0f / (float)BATCH);
            g_ticket = 0;                     // self-reset for graph replay
        }
    }
}

// ============================================================================
extern "C" void kernel_launch(void* const* d_in, const int* in_sizes, int n_in,
                              void* d_out, int out_size)
{
    const float* x      = (const float*)d_in[0];   // [64, 1500]
    const float* f_true = (const float*)d_in[1];   // [64]
    const float* fs     = (const float*)d_in[2];   // [64]
    float* out = (float*)d_out;                    // scalar

    dim3 g1(NCHUNKS, BATCH / 2);                   // (40, 32)
    fused_kernel<<<g1, 128>>>(x, fs, f_true, out);
}